// round 14
// baseline (speedup 1.0000x reference)
#include <cuda_runtime.h>
#include <stdint.h>

// RescaleProbMask: x (32, 256, 256, 16) fp32.
//   p[h,w] = mean over (batch, channel); out = scale(p)*x + bias(p).
//
// DRAM row-locality probe: every warp load is a 1KB SINGLE-PLANE contiguous
// run (vs 256-512B interleaved in prior kernels), at constant everything
// else (64B payload/lane, ld.global.nc.L2::evict_last.v4.b64 loads,
// st.global.wt.v4.b64 stores, regs<=32).
//
// Geometry: 512-thread CTA (16 warps), 16 pixels/tile (1KB per plane).
//   Warp w covers planes 2w and 2w+1: two 1KB warp loads.
//   Lane L: 8 floats per plane = channels [(L&1)*8,+8) of pixel L>>1.
//   Reduce: lane sum (2 planes) -> shfl_xor(1) (channel halves) ->
//   psum[16][17] smem (padded, conflict-free) -> barrier -> 16-warp sum
//   -> per-pixel (scale,bias) -> FMA -> write-through stores.

#define NB    32
#define NHW   (256 * 256)
#define NC    16
#define ALPHA 0.25f

#define PIX_PER_CTA 16
#define TILE_F      (PIX_PER_CTA * NC)      // 256 floats = 1KB per plane/tile
#define PLANE       ((size_t)NHW * NC)      // 1048576 floats per batch plane

__device__ __forceinline__ void ld_x32(const float* p, float* v) {
    uint64_t q0, q1, q2, q3;
    asm("ld.global.nc.L2::evict_last.v4.b64 {%0,%1,%2,%3}, [%4];"
        : "=l"(q0), "=l"(q1), "=l"(q2), "=l"(q3) : "l"(p));
    asm("mov.b64 {%0,%1}, %2;" : "=f"(v[0]), "=f"(v[1]) : "l"(q0));
    asm("mov.b64 {%0,%1}, %2;" : "=f"(v[2]), "=f"(v[3]) : "l"(q1));
    asm("mov.b64 {%0,%1}, %2;" : "=f"(v[4]), "=f"(v[5]) : "l"(q2));
    asm("mov.b64 {%0,%1}, %2;" : "=f"(v[6]), "=f"(v[7]) : "l"(q3));
}

__device__ __forceinline__ void st_out32_wt(float* p, const float* v) {
    uint64_t q0, q1, q2, q3;
    asm("mov.b64 %0, {%1,%2};" : "=l"(q0) : "f"(v[0]), "f"(v[1]));
    asm("mov.b64 %0, {%1,%2};" : "=l"(q1) : "f"(v[2]), "f"(v[3]));
    asm("mov.b64 %0, {%1,%2};" : "=l"(q2) : "f"(v[4]), "f"(v[5]));
    asm("mov.b64 %0, {%1,%2};" : "=l"(q3) : "f"(v[6]), "f"(v[7]));
    asm volatile("st.global.wt.v4.b64 [%0], {%1,%2,%3,%4};"
                 :: "l"(p), "l"(q0), "l"(q1), "l"(q2), "l"(q3) : "memory");
}

__global__ __launch_bounds__(512, 4)
void rescale_prob_mask_kernel(const float* __restrict__ x,
                              float* __restrict__ out) {
    __shared__ float psum[PIX_PER_CTA][17];   // padded: conflict-free

    const int tid  = threadIdx.x;
    const int warp = tid >> 5;                // 0..15
    const int lane = tid & 31;
    const int pix  = lane >> 1;               // pixel within CTA (0..15)

    // element offset of this lane's 8-float chunk within a batch plane
    const size_t off = (size_t)blockIdx.x * TILE_F + (size_t)lane * 8;

    const size_t i0 = (size_t)(warp * 2) * PLANE + off;   // plane 2w
    const size_t i1 = i0 + PLANE;                          // plane 2w+1

    float a[8], b[8];
    ld_x32(x + i0, a);      // 1KB contiguous per warp, single plane
    ld_x32(x + i1, b);      // 1KB contiguous per warp, single plane

    // lane-local partial sum (2 planes x 8 channels of pixel `pix`)
    float s = ((a[0] + a[1]) + (a[2] + a[3])) + ((a[4] + a[5]) + (a[6] + a[7]))
            + ((b[0] + b[1]) + (b[2] + b[3])) + ((b[4] + b[5]) + (b[6] + b[7]));

    // xor1: other channel half -> full pixel sum over this warp's 2 planes
    s += __shfl_xor_sync(0xffffffffu, s, 1);

    if ((lane & 1) == 0)
        psum[pix][warp] = s;
    __syncthreads();

    float tot = 0.0f;
    #pragma unroll
    for (int j = 0; j < 16; j++)
        tot += psum[pix][j];

    const float p = tot * (1.0f / (NB * NC));

    float scale, bias;
    if (p >= ALPHA) {
        scale = ALPHA / p;
        bias  = 0.0f;
    } else {
        const float beta = (1.0f - ALPHA) / (1.0f - p);
        scale = beta;
        bias  = 1.0f - beta;
    }

    #pragma unroll
    for (int k = 0; k < 8; k++) {
        a[k] = fmaf(scale, a[k], bias);
        b[k] = fmaf(scale, b[k], bias);
    }

    st_out32_wt(out + i0, a);
    st_out32_wt(out + i1, b);
}

extern "C" void kernel_launch(void* const* d_in, const int* in_sizes, int n_in,
                              void* d_out, int out_size) {
    const float* x   = (const float*)d_in[0];
    float*       out = (float*)d_out;

    const int blocks = NHW / PIX_PER_CTA;   // 4096
    rescale_prob_mask_kernel<<<blocks, 512>>>(x, out);
}